// round 15
// baseline (speedup 1.0000x reference)
#include <cuda_runtime.h>
#include <cuda_bf16.h>
#include <cstdint>

// Problem constants
#define BB   4
#define TT   2048
#define NC   4096
#define AA   8
#define SINK_ITERS 20
#define EPS_ 1e-5f
#define NTOK (BB * TT)         // 8192

// tensor-core logits tiling v4
#define TOKCTA 64
#define KSPLIT 32
#define DK     (NC / KSPLIT)   // 128
#define NTILES 128
#define ASTR   136             // ushorts
#define BSTR   136
#define NKC    (DK / 16)       // 8

// smem layout (ushort units)
#define A_HI_OFF 0
#define A_LO_OFF (TOKCTA * ASTR)                 // 8704
#define B_HI_OFF (2 * TOKCTA * ASTR)             // 17408
#define B_LO_OFF (B_HI_OFF + 24 * BSTR)          // 20672
#define SM_USHORTS (B_LO_OFF + 24 * BSTR)        // 23936 ushorts
#define SSQ_STRIDE 33
#define SMEM_TC_BYTES (SM_USHORTS * 2 + TOKCTA * SSQ_STRIDE * 4 + TOKCTA * 4)  // 56576 B

// ---------------- scratch ----------------
__device__ __align__(16) unsigned short g_hi[AA * 24 * NC];
__device__ __align__(16) unsigned short g_lo[AA * 24 * NC];
__device__ __align__(16) float part_buf[KSPLIT * 25 * NTOK];   // [ks][k(24)+ssq][token], 26.2 MB
__device__ __align__(16) float W_buf[NTOK * 16];

// ---------------- helpers ----------------
__device__ __forceinline__ void cp16(uint32_t dst, const void* src) {
    asm volatile("cp.async.cg.shared.global [%0], [%1], 16;" :: "r"(dst), "l"(src));
}
__device__ __forceinline__ void mma_bf16(float* c, uint32_t a0, uint32_t a1, uint32_t a2,
                                         uint32_t a3, uint32_t b0, uint32_t b1) {
    asm volatile("mma.sync.aligned.m16n8k16.row.col.f32.bf16.bf16.f32 "
                 "{%0,%1,%2,%3}, {%4,%5,%6,%7}, {%8,%9}, {%0,%1,%2,%3};"
                 : "+f"(c[0]), "+f"(c[1]), "+f"(c[2]), "+f"(c[3])
                 : "r"(a0), "r"(a1), "r"(a2), "r"(a3), "r"(b0), "r"(b1));
}
__device__ __forceinline__ uint32_t cvt_bf16x2(float hi, float lo) {
    uint32_t d;
    asm("cvt.rn.bf16x2.f32 %0, %1, %2;" : "=r"(d) : "f"(hi), "f"(lo));
    return d;
}

// ---------------- kernel 1: fold (coalesced, thread per (a, d-pair)) ----------------
__global__ void fold_tc(const float* __restrict__ wnorm,
                        const float* __restrict__ ppre, const float* __restrict__ ppost,
                        const float* __restrict__ pres,
                        const float* __restrict__ apre, const float* __restrict__ apost,
                        const float* __restrict__ ares) {
    const int idx = blockIdx.x * 128 + threadIdx.x;
    const int a = idx >> 11;
    const int d = (idx & 2047) * 2;
    const int ad0 = a * NC + d, ad1 = ad0 + 1;
    const float w0 = wnorm[ad0], w1 = wnorm[ad1];
    const float ap = apre[a], ao = apost[a], ar = ares[a];

    auto emit = [&](int k, float v0, float v1) {
        __nv_bfloat16 h0 = __float2bfloat16(v0);
        __nv_bfloat16 h1 = __float2bfloat16(v1);
        uint32_t hi = (uint32_t)__bfloat16_as_ushort(h0)
                    | ((uint32_t)__bfloat16_as_ushort(h1) << 16);
        uint32_t lo = cvt_bf16x2(v1 - __bfloat162float(h1), v0 - __bfloat162float(h0));
        size_t o = (size_t)(a * 24 + k) * NC + d;
        *(uint32_t*)(g_hi + o) = hi;
        *(uint32_t*)(g_lo + o) = lo;
    };

    float4 p0, p1;
    p0 = ((const float4*)ppre)[ad0]; p1 = ((const float4*)ppre)[ad1];
    emit(0, ap * w0 * p0.x, ap * w1 * p1.x);
    emit(1, ap * w0 * p0.y, ap * w1 * p1.y);
    emit(2, ap * w0 * p0.z, ap * w1 * p1.z);
    emit(3, ap * w0 * p0.w, ap * w1 * p1.w);
    p0 = ((const float4*)ppost)[ad0]; p1 = ((const float4*)ppost)[ad1];
    emit(4, ao * w0 * p0.x, ao * w1 * p1.x);
    emit(5, ao * w0 * p0.y, ao * w1 * p1.y);
    emit(6, ao * w0 * p0.z, ao * w1 * p1.z);
    emit(7, ao * w0 * p0.w, ao * w1 * p1.w);
#pragma unroll
    for (int q = 0; q < 4; ++q) {
        p0 = ((const float4*)pres)[(size_t)ad0 * 4 + q];
        p1 = ((const float4*)pres)[(size_t)ad1 * 4 + q];
        emit(8 + 4 * q,  ar * w0 * p0.x, ar * w1 * p1.x);
        emit(9 + 4 * q,  ar * w0 * p0.y, ar * w1 * p1.y);
        emit(10 + 4 * q, ar * w0 * p0.z, ar * w1 * p1.z);
        emit(11 + 4 * q, ar * w0 * p0.w, ar * w1 * p1.w);
    }
}

// ---------------- kernel 2: logits v4 — 8 warps, n-split MMA, k-major partials ----------------
__global__ void __launch_bounds__(256, 4)
logits_tc(const float* __restrict__ x, const int* __restrict__ aidx) {
    extern __shared__ __align__(16) unsigned short sm[];
    unsigned short* Ah = sm + A_HI_OFF;
    unsigned short* Al = sm + A_LO_OFF;
    unsigned short* Bh = sm + B_HI_OFF;
    unsigned short* Bl = sm + B_LO_OFF;
    float* ssq_sm = (float*)(sm + SM_USHORTS);
    float* ssq_fin = ssq_sm + TOKCTA * SSQ_STRIDE;

    const int tid = threadIdx.x;
    const int ks = blockIdx.x & (KSPLIT - 1);
    const int tt = blockIdx.x >> 5;
    const int t0 = tt * TOKCTA;
    const int aid = aidx[t0 >> 11];
    const int warp = tid >> 5, lane = tid & 31;

    // ---- B (phi hi/lo): 384 16B chunks each ----
    uint32_t sb = (uint32_t)__cvta_generic_to_shared(sm);
#pragma unroll
    for (int i = 0; i < 2; ++i) {
        int f = i * 256 + tid;
        if (f < 384) {
            int n = f >> 4, c = f & 15;
            size_t src = (size_t)(aid * 24 + n) * NC + ks * DK + c * 8;
            cp16(sb + (B_HI_OFF + n * BSTR + c * 8) * 2, g_hi + src);
            cp16(sb + (B_LO_OFF + n * BSTR + c * 8) * 2, g_lo + src);
        }
    }
    asm volatile("cp.async.commit_group;");

    // ---- A: 8 rows per warp, coalesced, truncation split ----
    {
        const float* xbase = x + (size_t)t0 * NC + ks * DK;
#pragma unroll 4
        for (int r = 0; r < 8; ++r) {
            const int row = warp * 8 + r;
            float4 v = *((const float4*)(xbase + (size_t)row * NC) + lane);
            float ps = v.x * v.x + v.y * v.y + v.z * v.z + v.w * v.w;

            uint32_t u0 = __float_as_uint(v.x), u1 = __float_as_uint(v.y);
            uint32_t u2 = __float_as_uint(v.z), u3 = __float_as_uint(v.w);
            uint32_t h01 = __byte_perm(u0, u1, 0x7632);
            uint32_t h23 = __byte_perm(u2, u3, 0x7632);
            float f0 = __uint_as_float(u0 & 0xffff0000u);
            float f1 = __uint_as_float(u1 & 0xffff0000u);
            float f2 = __uint_as_float(u2 & 0xffff0000u);
            float f3 = __uint_as_float(u3 & 0xffff0000u);
            uint32_t l01 = cvt_bf16x2(v.y - f1, v.x - f0);
            uint32_t l23 = cvt_bf16x2(v.w - f3, v.z - f2);

            *(uint2*)(Ah + row * ASTR + lane * 4) = make_uint2(h01, h23);
            *(uint2*)(Al + row * ASTR + lane * 4) = make_uint2(l01, l23);
            ssq_sm[row * SSQ_STRIDE + lane] = ps;
        }
    }

    asm volatile("cp.async.wait_group 0;");
    __syncthreads();

    if (tid < TOKCTA) {
        const float* rp = ssq_sm + tid * SSQ_STRIDE;
        float s = 0.0f;
#pragma unroll 8
        for (int l = 0; l < 32; ++l) s += rp[l];
        ssq_fin[tid] = s;
    }

    // ---- MMA: warps 0-3 -> nt {0,1}; warps 4-7 -> nt {2} (same rows) ----
    const int g = lane >> 2, t = lane & 3;
    const int wlo = warp & 3;
    const int grow = wlo * 16;
    const bool hiw = warp >= 4;

    const unsigned short* ArH  = Ah + (grow + g) * ASTR + 2 * t;
    const unsigned short* ArH8 = ArH + 8 * ASTR;
    const unsigned short* ArL  = Al + (grow + g) * ASTR + 2 * t;
    const unsigned short* ArL8 = ArL + 8 * ASTR;

    float acc0[4] = {0, 0, 0, 0};   // nt0 (low warps) or nt2 (high warps)
    float acc1[4] = {0, 0, 0, 0};   // nt1 (low warps only)

#pragma unroll
    for (int kc = 0; kc < NKC; ++kc) {
        const int k0 = kc * 16;
        uint32_t ah0 = *(const uint32_t*)(ArH  + k0);
        uint32_t ah1 = *(const uint32_t*)(ArH8 + k0);
        uint32_t ah2 = *(const uint32_t*)(ArH  + k0 + 8);
        uint32_t ah3 = *(const uint32_t*)(ArH8 + k0 + 8);
        uint32_t al0 = *(const uint32_t*)(ArL  + k0);
        uint32_t al1 = *(const uint32_t*)(ArL8 + k0);
        uint32_t al2 = *(const uint32_t*)(ArL  + k0 + 8);
        uint32_t al3 = *(const uint32_t*)(ArL8 + k0 + 8);

        const int nta = hiw ? 2 : 0;
        {
            const unsigned short* brh = Bh + (nta * 8 + g) * BSTR + 2 * t + k0;
            const unsigned short* brl = Bl + (nta * 8 + g) * BSTR + 2 * t + k0;
            uint32_t bh0 = *(const uint32_t*)(brh);
            uint32_t bh1 = *(const uint32_t*)(brh + 8);
            uint32_t bl0 = *(const uint32_t*)(brl);
            uint32_t bl1 = *(const uint32_t*)(brl + 8);
            mma_bf16(acc0, ah0, ah1, ah2, ah3, bh0, bh1);
            mma_bf16(acc0, ah0, ah1, ah2, ah3, bl0, bl1);
            mma_bf16(acc0, al0, al1, al2, al3, bh0, bh1);
        }
        if (!hiw) {
            const unsigned short* brh = Bh + (8 + g) * BSTR + 2 * t + k0;
            const unsigned short* brl = Bl + (8 + g) * BSTR + 2 * t + k0;
            uint32_t bh0 = *(const uint32_t*)(brh);
            uint32_t bh1 = *(const uint32_t*)(brh + 8);
            uint32_t bl0 = *(const uint32_t*)(brl);
            uint32_t bl1 = *(const uint32_t*)(brl + 8);
            mma_bf16(acc1, ah0, ah1, ah2, ah3, bh0, bh1);
            mma_bf16(acc1, ah0, ah1, ah2, ah3, bl0, bl1);
            mma_bf16(acc1, al0, al1, al2, al3, bh0, bh1);
        }
    }

    __syncthreads();   // ssq_fin ready

    // ---- epilogue: k-major partials [ks][25][8192] ----
    const int r1 = t0 + grow + g, r2 = r1 + 8;
    float* base = part_buf + (size_t)ks * 25 * NTOK;
    if (!hiw) {
        base[(0 + 2 * t) * NTOK + r1] = acc0[0];
        base[(1 + 2 * t) * NTOK + r1] = acc0[1];
        base[(0 + 2 * t) * NTOK + r2] = acc0[2];
        base[(1 + 2 * t) * NTOK + r2] = acc0[3];
        base[(8 + 2 * t) * NTOK + r1] = acc1[0];
        base[(9 + 2 * t) * NTOK + r1] = acc1[1];
        base[(8 + 2 * t) * NTOK + r2] = acc1[2];
        base[(9 + 2 * t) * NTOK + r2] = acc1[3];
    } else {
        base[(16 + 2 * t) * NTOK + r1] = acc0[0];
        base[(17 + 2 * t) * NTOK + r1] = acc0[1];
        base[(16 + 2 * t) * NTOK + r2] = acc0[2];
        base[(17 + 2 * t) * NTOK + r2] = acc0[3];
        if (t == 0) {
            base[24 * NTOK + r1] = ssq_fin[grow + g];
            base[24 * NTOK + r2] = ssq_fin[grow + g + 8];
        }
    }
}

// ---------------- kernel 3: finalize (coalesced k-major reads, sinkhorn -> W) ----------------
__global__ void finalize_k(const float* __restrict__ bpre, const float* __restrict__ bpost,
                           const float* __restrict__ bres, const int* __restrict__ aidx) {
    const int t = blockIdx.x * 128 + threadIdx.x;
    const int aid = aidx[t >> 11];

    float a[24];
#pragma unroll
    for (int k = 0; k < 24; ++k) a[k] = 0.0f;
    float ssq = 0.0f;
#pragma unroll 4
    for (int ks = 0; ks < KSPLIT; ++ks) {
        const float* base = part_buf + (size_t)ks * 25 * NTOK + t;
#pragma unroll
        for (int k = 0; k < 24; ++k) a[k] += base[k * NTOK];
        ssq += base[24 * NTOK];
    }
    float rinv = rsqrtf(ssq * (1.0f / 4096.0f) + EPS_);

    float hpre[4], hpost[4];
#pragma unroll
    for (int n = 0; n < 4; ++n)
        hpre[n] = 1.0f / (1.0f + expf(-(a[n] * rinv + bpre[aid * 4 + n])));
#pragma unroll
    for (int n = 0; n < 4; ++n)
        hpost[n] = 2.0f / (1.0f + expf(-(a[4 + n] * rinv + bpost[aid * 4 + n])));

    float m[16];
#pragma unroll
    for (int ij = 0; ij < 16; ++ij)
        m[ij] = expf(a[8 + ij] * rinv + bres[aid * 16 + ij]);

    for (int it = 0; it < SINK_ITERS; ++it) {
#pragma unroll
        for (int i = 0; i < 4; ++i) {
            float r = 1.0f / (m[i * 4] + m[i * 4 + 1] + m[i * 4 + 2] + m[i * 4 + 3]);
            m[i * 4] *= r; m[i * 4 + 1] *= r; m[i * 4 + 2] *= r; m[i * 4 + 3] *= r;
        }
#pragma unroll
        for (int j = 0; j < 4; ++j) {
            float r = 1.0f / (m[j] + m[4 + j] + m[8 + j] + m[12 + j]);
            m[j] *= r; m[4 + j] *= r; m[8 + j] *= r; m[12 + j] *= r;
        }
    }

    float4* wd = (float4*)(W_buf + (size_t)t * 16);
#pragma unroll
    for (int i = 0; i < 4; ++i)
        wd[i] = make_float4(m[i * 4 + 0] + hpost[i] * hpre[0],
                            m[i * 4 + 1] + hpost[i] * hpre[1],
                            m[i * 4 + 2] + hpost[i] * hpre[2],
                            m[i * 4 + 3] + hpost[i] * hpre[3]);
}

// ---------------- kernel 4: out[token] = W @ x[token] ----------------
__global__ void out_k(const float* __restrict__ x, float* __restrict__ out) {
    const int token = (NTOK - 1) - blockIdx.x;
    __shared__ float sW[16];
    if (threadIdx.x < 16) sW[threadIdx.x] = W_buf[(size_t)token * 16 + threadIdx.x];
    __syncthreads();
    const float4* xr = (const float4*)(x + (size_t)token * NC);
    float4* orow = (float4*)(out + (size_t)token * NC);
    const int c = threadIdx.x;
    float4 xv0 = xr[c], xv1 = xr[256 + c], xv2 = xr[512 + c], xv3 = xr[768 + c];
#pragma unroll
    for (int i = 0; i < 4; ++i) {
        float w0 = sW[i * 4], w1 = sW[i * 4 + 1], w2 = sW[i * 4 + 2], w3 = sW[i * 4 + 3];
        float4 o;
        o.x = w0 * xv0.x + w1 * xv1.x + w2 * xv2.x + w3 * xv3.x;
        o.y = w0 * xv0.y + w1 * xv1.y + w2 * xv2.y + w3 * xv3.y;
        o.z = w0 * xv0.z + w1 * xv1.z + w2 * xv2.z + w3 * xv3.z;
        o.w = w0 * xv0.w + w1 * xv1.w + w2 * xv2.w + w3 * xv3.w;
        orow[i * 256 + c] = o;
    }
}

// ---------------- launch ----------------
extern "C" void kernel_launch(void* const* d_in, const int* in_sizes, int n_in,
                              void* d_out, int out_size) {
    const float* x     = (const float*)d_in[0];
    const float* wnorm = (const float*)d_in[1];
    const float* ppre  = (const float*)d_in[2];
    const float* ppost = (const float*)d_in[3];
    const float* pres  = (const float*)d_in[4];
    const float* bpre  = (const float*)d_in[5];
    const float* bpost = (const float*)d_in[6];
    const float* bres  = (const float*)d_in[7];
    const float* apre  = (const float*)d_in[8];
    const float* apost = (const float*)d_in[9];
    const float* ares  = (const float*)d_in[10];
    const int*   aidx  = (const int*)d_in[11];
    float* out = (float*)d_out;

    cudaFuncSetAttribute(logits_tc, cudaFuncAttributeMaxDynamicSharedMemorySize, SMEM_TC_BYTES);

    fold_tc<<<AA * NC / 2 / 128, 128>>>(wnorm, ppre, ppost, pres, apre, apost, ares);
    logits_tc<<<NTILES * KSPLIT, 256, SMEM_TC_BYTES>>>(x, aidx);
    finalize_k<<<NTOK / 128, 128>>>(bpre, bpost, bres, aidx);
    out_k<<<NTOK, 256>>>(x, out);
}

// round 16
// speedup vs baseline: 1.1910x; 1.1910x over previous
#include <cuda_runtime.h>
#include <cstdint>

// Problem constants
#define BB   4
#define TT   2048
#define NC   4096
#define AA   8
#define SINK_ITERS 20
#define EPS_ 1e-5f

// logits tiling (the best-measured R3/R11 config)
#define TOK    32            // tokens per CTA
#define DT     128           // d-tile
#define KSPLIT 8
#define DPART  (NC / KSPLIT) // 512
#define TILES  (DPART / DT)  // 4
#define XROWF  136           // x smem row stride (floats)
#define PROWF  28            // phi smem row stride (floats)
#define PARTW  28            // partial row: 24 logits + ssq + pad

#define XT (TOK * XROWF)     // 4352 floats
#define PT (DT * PROWF)      // 3584 floats
#define BUFF (XT + PT)       // 7936 floats
#define SMEM_BYTES (2 * BUFF * 4)

// ---------------- scratch ----------------
__device__ __align__(16) float g_buf[AA * NC * 24];                 // folded phi [a][d][24]
__device__ __align__(16) float part_buf[KSPLIT * BB * TT * PARTW];  // 7.3 MB
__device__ __align__(16) float W_buf[BB * TT * 16];

// ---------------- helpers ----------------
typedef unsigned long long ull;
__device__ __forceinline__ void ffma2(ull& d, ull a, ull b) {
    asm("fma.rn.f32x2 %0, %1, %2, %0;" : "+l"(d) : "l"(a), "l"(b));
}
__device__ __forceinline__ void fadd2(ull& d, ull a, ull b) {
    asm("add.rn.f32x2 %0, %1, %2;" : "=l"(d) : "l"(a), "l"(b));
}
__device__ __forceinline__ ull dup2(float v) {
    ull r; asm("mov.b64 %0, {%1, %1};" : "=l"(r) : "f"(v)); return r;
}
__device__ __forceinline__ void unpack2(ull u, float& lo, float& hi) {
    asm("mov.b64 {%0, %1}, %2;" : "=f"(lo), "=f"(hi) : "l"(u));
}
__device__ __forceinline__ void cp16(uint32_t dst, const void* src) {
    asm volatile("cp.async.cg.shared.global [%0], [%1], 16;" :: "r"(dst), "l"(src));
}

// ---------------- kernel 1: fold alpha*w*phi -> g_buf[a][d][24] (fast, coalesced) ----------------
__global__ void fold_k(const float* __restrict__ wnorm,
                       const float* __restrict__ ppre, const float* __restrict__ ppost,
                       const float* __restrict__ pres,
                       const float* __restrict__ apre, const float* __restrict__ apost,
                       const float* __restrict__ ares) {
    int idx = blockIdx.x * 256 + threadIdx.x;    // (a,d)*6 + c
    if (idx >= AA * NC * 6) return;
    int c = idx % 6;
    int ad = idx / 6;
    int a = ad >> 12;
    float wv = wnorm[ad];
    float coef = ((c == 0) ? apre[a] : (c == 1) ? apost[a] : ares[a]) * wv;
    float4 v = (c == 0) ? ((const float4*)ppre)[ad]
             : (c == 1) ? ((const float4*)ppost)[ad]
                        : ((const float4*)pres)[(size_t)ad * 4 + (c - 2)];
    ((float4*)g_buf)[idx] = make_float4(coef * v.x, coef * v.y, coef * v.z, coef * v.w);
}

// ---------------- kernel 2: partial logits (R3 exact inner loop) ----------------
// grid = 2048: blockIdx.x = tt*KSPLIT + ks. 128 threads:
//   s = tid&7 (d-slice), tg = (tid>>3)&7 (token group: tokens tg+8j), kh = tid>>6 (k half)
__global__ void __launch_bounds__(128, 3)
logits_k(const float* __restrict__ x, const int* __restrict__ aidx) {
    extern __shared__ float smem[];
    const int tid = threadIdx.x;
    const int ks = blockIdx.x & (KSPLIT - 1);
    const int tt = blockIdx.x >> 3;
    const int b  = tt >> 6;
    const int t0 = (tt & 63) * TOK;
    const int aid = aidx[b];
    const int s = tid & 7, tg = (tid >> 3) & 7, kh = tid >> 6;

    const float* xb = x + ((size_t)(b * TT + t0)) * NC + ks * DPART;
    const float* gb = g_buf + ((size_t)aid * NC + ks * DPART) * 24;

    uint32_t sbase = (uint32_t)__cvta_generic_to_shared(smem);
    const uint32_t xbase[2] = { sbase,          sbase + BUFF * 4 };
    const uint32_t pbase[2] = { sbase + XT * 4, sbase + (BUFF + XT) * 4 };

    ull acc[24];
#pragma unroll
    for (int k = 0; k < 24; ++k) acc[k] = 0ull;
    ull ssq[4] = {0ull, 0ull, 0ull, 0ull};

    auto copy_tile = [&](int tile, int bi) {
        const int d0 = tile * DT;
#pragma unroll
        for (int i2 = 0; i2 < 8; ++i2) {            // x: 1024 float4
            int f = i2 * 128 + tid;
            int tok = f >> 5, q = f & 31;
            cp16(xbase[bi] + tok * (XROWF * 4) + q * 16,
                 xb + (size_t)tok * NC + d0 + q * 4);
        }
#pragma unroll
        for (int i2 = 0; i2 < 6; ++i2) {            // phi: 768 float4
            int f = i2 * 128 + tid;
            int d = f / 6, c = f - d * 6;
            cp16(pbase[bi] + d * (PROWF * 4) + c * 16,
                 gb + (size_t)(d0 + d) * 24 + c * 4);
        }
        asm volatile("cp.async.commit_group;");
    };

    copy_tile(0, 0);

    for (int t = 0; t < TILES; ++t) {
        if (t + 1 < TILES) {
            copy_tile(t + 1, (t + 1) & 1);
            asm volatile("cp.async.wait_group 1;");
        } else {
            asm volatile("cp.async.wait_group 0;");
        }
        __syncthreads();

        const float* xs = smem + (t & 1) * BUFF;
        const float* ps = xs + XT;
        const float* xr0 = xs + (tg     ) * XROWF;
        const float* xr1 = xs + (tg +  8) * XROWF;
        const float* xr2 = xs + (tg + 16) * XROWF;
        const float* xr3 = xs + (tg + 24) * XROWF;

#pragma unroll 4
        for (int i = 0; i < 16; ++i) {
            const int dd = i * 8 + s;
            ull x0 = dup2(xr0[dd]);
            ull x1 = dup2(xr1[dd]);
            ull x2 = dup2(xr2[dd]);
            ull x3 = dup2(xr3[dd]);
            if (kh == 0) {
                ffma2(ssq[0], x0, x0); ffma2(ssq[1], x1, x1);
                ffma2(ssq[2], x2, x2); ffma2(ssq[3], x3, x3);
            }
            const ulonglong2* pp = (const ulonglong2*)(ps + dd * PROWF + kh * 12);
            ulonglong2 pA = pp[0], pB = pp[1], pC = pp[2];
            ffma2(acc[0],  x0, pA.x); ffma2(acc[6],  x1, pA.x);
            ffma2(acc[12], x2, pA.x); ffma2(acc[18], x3, pA.x);
            ffma2(acc[1],  x0, pA.y); ffma2(acc[7],  x1, pA.y);
            ffma2(acc[13], x2, pA.y); ffma2(acc[19], x3, pA.y);
            ffma2(acc[2],  x0, pB.x); ffma2(acc[8],  x1, pB.x);
            ffma2(acc[14], x2, pB.x); ffma2(acc[20], x3, pB.x);
            ffma2(acc[3],  x0, pB.y); ffma2(acc[9],  x1, pB.y);
            ffma2(acc[15], x2, pB.y); ffma2(acc[21], x3, pB.y);
            ffma2(acc[4],  x0, pC.x); ffma2(acc[10], x1, pC.x);
            ffma2(acc[16], x2, pC.x); ffma2(acc[22], x3, pC.x);
            ffma2(acc[5],  x0, pC.y); ffma2(acc[11], x1, pC.y);
            ffma2(acc[17], x2, pC.y); ffma2(acc[23], x3, pC.y);
        }
        __syncthreads();
    }

    // reduce over the 8 d-slices (lane bits 0..2)
#pragma unroll
    for (int k = 0; k < 24; ++k) {
#pragma unroll
        for (int m = 1; m < 8; m <<= 1) {
            ull o = __shfl_xor_sync(0xffffffffu, acc[k], m);
            fadd2(acc[k], acc[k], o);
        }
    }
    if (kh == 0) {
#pragma unroll
        for (int j = 0; j < 4; ++j) {
#pragma unroll
            for (int m = 1; m < 8; m <<= 1) {
                ull o = __shfl_xor_sync(0xffffffffu, ssq[j], m);
                fadd2(ssq[j], ssq[j], o);
            }
        }
    }

    if (s == 0) {
        const int tbase = b * TT + t0 + tg;
#pragma unroll
        for (int j = 0; j < 4; ++j) {
            float* pa = part_buf + ((size_t)ks * (BB * TT) + tbase + 8 * j) * PARTW;
            float v[12];
#pragma unroll
            for (int c = 0; c < 6; ++c) {
                float lo, hi; unpack2(acc[j * 6 + c], lo, hi);
                v[2 * c]     = lo;
                v[2 * c + 1] = hi;
            }
            // 3 x STG.128 instead of 12 scalar stores (kh halves are 16B-aligned: kh*12 floats)
            float4* pv = (float4*)(pa + kh * 12);
            pv[0] = make_float4(v[0], v[1], v[2], v[3]);
            pv[1] = make_float4(v[4], v[5], v[6], v[7]);
            pv[2] = make_float4(v[8], v[9], v[10], v[11]);
            if (kh == 0) {
                float lo, hi; unpack2(ssq[j], lo, hi);
                pa[24] = lo;   // duplicated lanes: lo == hi == true sum
            }
        }
    }
}

// ---------------- kernel 3: finalize (reduce splits, sinkhorn -> W) ----------------
__global__ void finalize_k(const float* __restrict__ bpre, const float* __restrict__ bpost,
                           const float* __restrict__ bres, const int* __restrict__ aidx) {
    const int t = blockIdx.x * 128 + threadIdx.x;
    const int aid = aidx[t >> 11];

    float a[24];
#pragma unroll
    for (int k = 0; k < 24; ++k) a[k] = 0.0f;
    float ssq = 0.0f;
#pragma unroll
    for (int ks = 0; ks < KSPLIT; ++ks) {
        const float4* p = (const float4*)(part_buf + ((size_t)ks * (BB * TT) + t) * PARTW);
#pragma unroll
        for (int q = 0; q < 6; ++q) {
            float4 v = p[q];
            a[q * 4 + 0] += v.x; a[q * 4 + 1] += v.y;
            a[q * 4 + 2] += v.z; a[q * 4 + 3] += v.w;
        }
        ssq += p[6].x;
    }
    float rinv = rsqrtf(ssq * (1.0f / 4096.0f) + EPS_);

    float hpre[4], hpost[4];
#pragma unroll
    for (int n = 0; n < 4; ++n)
        hpre[n] = 1.0f / (1.0f + expf(-(a[n] * rinv + bpre[aid * 4 + n])));
#pragma unroll
    for (int n = 0; n < 4; ++n)
        hpost[n] = 2.0f / (1.0f + expf(-(a[4 + n] * rinv + bpost[aid * 4 + n])));

    float m[16];
#pragma unroll
    for (int ij = 0; ij < 16; ++ij)
        m[ij] = expf(a[8 + ij] * rinv + bres[aid * 16 + ij]);

    for (int it = 0; it < SINK_ITERS; ++it) {
#pragma unroll
        for (int i = 0; i < 4; ++i) {
            float r = 1.0f / (m[i * 4] + m[i * 4 + 1] + m[i * 4 + 2] + m[i * 4 + 3]);
            m[i * 4] *= r; m[i * 4 + 1] *= r; m[i * 4 + 2] *= r; m[i * 4 + 3] *= r;
        }
#pragma unroll
        for (int j = 0; j < 4; ++j) {
            float r = 1.0f / (m[j] + m[4 + j] + m[8 + j] + m[12 + j]);
            m[j] *= r; m[4 + j] *= r; m[8 + j] *= r; m[12 + j] *= r;
        }
    }

    float4* wd = (float4*)(W_buf + (size_t)t * 16);
#pragma unroll
    for (int i = 0; i < 4; ++i)
        wd[i] = make_float4(m[i * 4 + 0] + hpost[i] * hpre[0],
                            m[i * 4 + 1] + hpost[i] * hpre[1],
                            m[i * 4 + 2] + hpost[i] * hpre[2],
                            m[i * 4 + 3] + hpost[i] * hpre[3]);
}

// ---------------- kernel 4: out[token] = W @ x[token] (reversed order) ----------------
__global__ void out_k(const float* __restrict__ x, float* __restrict__ out) {
    const int token = (BB * TT - 1) - blockIdx.x;
    __shared__ float sW[16];
    if (threadIdx.x < 16) sW[threadIdx.x] = W_buf[(size_t)token * 16 + threadIdx.x];
    __syncthreads();
    const float4* xr = (const float4*)(x + (size_t)token * NC);
    float4* orow = (float4*)(out + (size_t)token * NC);
    const int c = threadIdx.x;
    float4 xv0 = xr[c], xv1 = xr[256 + c], xv2 = xr[512 + c], xv3 = xr[768 + c];
#pragma unroll
    for (int i = 0; i < 4; ++i) {
        float w0 = sW[i * 4], w1 = sW[i * 4 + 1], w2 = sW[i * 4 + 2], w3 = sW[i * 4 + 3];
        float4 o;
        o.x = w0 * xv0.x + w1 * xv1.x + w2 * xv2.x + w3 * xv3.x;
        o.y = w0 * xv0.y + w1 * xv1.y + w2 * xv2.y + w3 * xv3.y;
        o.z = w0 * xv0.z + w1 * xv1.z + w2 * xv2.z + w3 * xv3.z;
        o.w = w0 * xv0.w + w1 * xv1.w + w2 * xv2.w + w3 * xv3.w;
        orow[i * 256 + c] = o;
    }
}

// ---------------- launch ----------------
extern "C" void kernel_launch(void* const* d_in, const int* in_sizes, int n_in,
                              void* d_out, int out_size) {
    const float* x     = (const float*)d_in[0];
    const float* wnorm = (const float*)d_in[1];
    const float* ppre  = (const float*)d_in[2];
    const float* ppost = (const float*)d_in[3];
    const float* pres  = (const float*)d_in[4];
    const float* bpre  = (const float*)d_in[5];
    const float* bpost = (const float*)d_in[6];
    const float* bres  = (const float*)d_in[7];
    const float* apre  = (const float*)d_in[8];
    const float* apost = (const float*)d_in[9];
    const float* ares  = (const float*)d_in[10];
    const int*   aidx  = (const int*)d_in[11];
    float* out = (float*)d_out;

    cudaFuncSetAttribute(logits_k, cudaFuncAttributeMaxDynamicSharedMemorySize, SMEM_BYTES);

    fold_k<<<(AA * NC * 6 + 255) / 256, 256>>>(wnorm, ppre, ppost, pres, apre, apost, ares);
    logits_k<<<(BB * TT / TOK) * KSPLIT, 128, SMEM_BYTES>>>(x, aidx);
    finalize_k<<<BB * TT / 128, 128>>>(bpre, bpost, bres, aidx);
    out_k<<<BB * TT, 256>>>(x, out);
}